// round 11
// baseline (speedup 1.0000x reference)
#include <cuda_runtime.h>
#include <math.h>

#define NN 20000
#define FF 8
#define PP 12
#define OO 32
#define EE 320000
#define FP 96           // F*P floats per node row
#define CH 24           // float4 chunks per row
#define SLOTS 96        // max in-degree slots (Poisson(16); guarded)
#define NSM 148
#define NBPS 4
#define NBLK (NSM * NBPS)            // 592 blocks, all co-resident
#define NTHR 256
#define WPB (NTHR / 32)              // 8 warps per block
#define NWARP (NBLK * WPB)           // 4736 warps
#define FULL 0xffffffffu

// ---- scratch (static device globals; no allocation allowed) ----
__device__ int      g_cnt[NN];            // in-degree (atomic counters)
__device__ __align__(8) int2 g_slot[NN * SLOTS];  // (src col, weight bits) per dst slot
__device__ int      g_hdr[NN];            // (deg4/4)<<24 | true_deg
__device__ float    g_cwz[FF * OO];       // fused Wz @ Lz^T
__device__ float    g_cwh[FF * OO];       // fused Wh @ Lh^T
__device__ float    g_cbz[OO];
__device__ float    g_cbh[OO];
__device__ float    g_probs[PP];
__device__ unsigned g_node_ctr;           // P3 dynamic work counter (reset in P2b)
__device__ unsigned g_bar[3];             // monotonic barrier counters (never reset)

// Monotonic grid barrier: all NBLK blocks co-resident (4/SM via launch bounds).
__device__ __forceinline__ void grid_barrier(int id) {
    __syncthreads();
    if (threadIdx.x == 0) {
        __threadfence();                                      // release
        unsigned arrived = atomicAdd(&g_bar[id], 1u) + 1u;
        unsigned target  = ((arrived + NBLK - 1u) / NBLK) * NBLK;
        while (*(volatile unsigned*)&g_bar[id] < target) { }
        __threadfence();                                      // acquire
    }
    __syncthreads();
}

// Packed fp32x2 helpers (Blackwell FFMA2 — only reachable via PTX)
__device__ __forceinline__ unsigned long long pack2(float lo, float hi) {
    unsigned long long r;
    asm("mov.b64 %0, {%1, %2};" : "=l"(r) : "f"(lo), "f"(hi));
    return r;
}
__device__ __forceinline__ void unpack2(unsigned long long v, float& lo, float& hi) {
    asm("mov.b64 {%0, %1}, %2;" : "=f"(lo), "=f"(hi) : "l"(v));
}
__device__ __forceinline__ unsigned long long ffma2(
        unsigned long long a, unsigned long long b, unsigned long long c) {
    unsigned long long d;
    asm("fma.rn.f32x2 %0, %1, %2, %3;" : "=l"(d) : "l"(a), "l"(b), "l"(c));
    return d;
}
// HW tanh (MUFU.TANH), rel err ~1e-5 — far inside the 1e-3 budget
__device__ __forceinline__ float htanh(float x) {
    float r;
    asm("tanh.approx.f32 %0, %1;" : "=f"(r) : "f"(x));
    return r;
}

__global__ void __launch_bounds__(NTHR, NBPS) fused_kernel(
        const float* __restrict__ x,
        const int*   __restrict__ ei,
        const float* __restrict__ Wz,  const float* __restrict__ bz,
        const float* __restrict__ Wh,  const float* __restrict__ bh,
        const float* __restrict__ lzw, const float* __restrict__ lzb,
        const float* __restrict__ lhw, const float* __restrict__ lhb,
        const float* __restrict__ att,
        const float* __restrict__ out_w, const float* __restrict__ out_b,
        float* __restrict__ out) {
    const int t    = threadIdx.x;
    const int lane = t & 31;
    const int warp = t >> 5;                 // 0..7
    const int gid  = blockIdx.x * NTHR + t;
    const int T    = NBLK * NTHR;
    const int gwarp = blockIdx.x * WPB + warp;

    __shared__ float buf[WPB][FP];           // GRU staging, per warp
    __shared__ float sow[PP * OO];           // staged out_w
    __shared__ float sob[PP];                // staged out_b
    __shared__ float sp2[PP];                // 0.5 * softmax(att)

    // ---------------- P0: zero counters + fold weights (blocks 0..2) -------
    for (int j = gid; j < NN; j += T) g_cnt[j] = 0;

    if (blockIdx.x == 0) {                   // W'_z[f][o] = sum_k Wz[f][k]*lzw[o][k]
        int f = t >> 5, o = t & 31;
        float s = 0.f;
        #pragma unroll
        for (int k = 0; k < 32; ++k) s = fmaf(Wz[f * 32 + k], lzw[o * 64 + k], s);
        g_cwz[t] = s;
    } else if (blockIdx.x == 1) {            // W'_h
        int f = t >> 5, o = t & 31;
        float s = 0.f;
        #pragma unroll
        for (int k = 0; k < 32; ++k) s = fmaf(Wh[f * 32 + k], lhw[o * 64 + k], s);
        g_cwh[t] = s;
    } else if (blockIdx.x == 2) {
        if (t < 32) {                        // b'_z
            float s = lzb[t];
            #pragma unroll
            for (int k = 0; k < 32; ++k) s = fmaf(bz[k], lzw[t * 64 + k], s);
            g_cbz[t] = s;
        } else if (t < 64) {                 // b'_h
            int o = t - 32;
            float s = lhb[o];
            #pragma unroll
            for (int k = 0; k < 32; ++k) s = fmaf(bh[k], lhw[o * 64 + k], s);
            g_cbh[o] = s;
        } else if (t == 64) {                // softmax over 12 logits
            float m = att[0];
            for (int p = 1; p < PP; ++p) m = fmaxf(m, att[p]);
            float e[PP], sum = 0.f;
            for (int p = 0; p < PP; ++p) { e[p] = __expf(att[p] - m); sum += e[p]; }
            float inv = 1.f / sum;
            for (int p = 0; p < PP; ++p) g_probs[p] = e[p] * inv;
        }
        if (t == 65) g_node_ctr = 0;         // reset P3 work counter
    }
    grid_barrier(0);

    // ---------------- P1: slotted scatter of src cols -----------------------
    {
        const int4* s4p = (const int4*)ei;
        const int4* d4p = (const int4*)(ei + EE);
        for (int q = gid; q < EE / 4; q += T) {
            int4 s4 = s4p[q];
            int4 d4 = d4p[q];
            int p0 = atomicAdd(&g_cnt[d4.x], 1);
            int p1 = atomicAdd(&g_cnt[d4.y], 1);
            int p2 = atomicAdd(&g_cnt[d4.z], 1);
            int p3 = atomicAdd(&g_cnt[d4.w], 1);
            if (p0 < SLOTS) g_slot[d4.x * SLOTS + p0].x = s4.x;
            if (p1 < SLOTS) g_slot[d4.y * SLOTS + p1].x = s4.y;
            if (p2 < SLOTS) g_slot[d4.z * SLOTS + p2].x = s4.z;
            if (p3 < SLOTS) g_slot[d4.w * SLOTS + p3].x = s4.w;
        }
    }
    grid_barrier(1);

    // ---------------- P2b: per-slot weights + padding + header -------------
    // warp per node: w = rsqrt(cnt[col]+1), zero-weight padding to mult of 4,
    // header packs (deg4/4, true deg). Absorbs the col->dinv hop here at
    // full parallelism instead of once per edge batch in P3.
    for (int node = gwarp; node < NN; node += NWARP) {
        int deg  = __ldcg(&g_cnt[node]);
        int degc = deg > SLOTS ? SLOTS : deg;
        int deg4 = (degc + 3) & ~3;
        int2* slots = g_slot + node * SLOTS;
        for (int b = lane; b < deg4; b += 32) {
            int2 s;
            if (b < degc) {
                int c = slots[b].x;
                s.x = c;
                s.y = __float_as_int(rsqrtf((float)(__ldcg(&g_cnt[c]) + 1)));
            } else {
                s.x = 0; s.y = 0;            // zero weight padding
            }
            slots[b] = s;
        }
        if (lane == 0) g_hdr[node] = ((deg4 >> 2) << 24) | deg;
    }
    grid_barrier(2);

    // ---------------- P3: gather + GRU + attention + readout ---------------
    {
        if (t < PP) sp2[t] = 0.5f * g_probs[t];   // fold sigmoid's 0.5
        if (t < PP) sob[t] = out_b[t];
        for (int j = t; j < PP * OO; j += NTHR) sow[j] = out_w[j];
        __syncthreads();

        float wz[FF], wh[FF];
        #pragma unroll
        for (int f = 0; f < FF; ++f) {
            wz[f] = g_cwz[f * OO + lane];
            wh[f] = g_cwh[f * OO + lane];
        }
        const float bz_ = g_cbz[lane];
        const float bh_ = g_cbh[lane];

        for (;;) {
            int base;
            if (lane == 0) base = (int)atomicAdd(&g_node_ctr, 2u);
            base = __shfl_sync(FULL, base, 0);
            if (base >= NN) break;
            int nend = base + 2 < NN ? base + 2 : NN;

            for (int node = base; node < nend; ++node) {
                const int2* slots = g_slot + node * SLOTS;
                // header and first slot batch load CONCURRENTLY (independent)
                int  hdr = __ldg(&g_hdr[node]);
                int2 sl  = __ldg(&slots[lane]);     // SLOTS >= 32: always in bounds
                int  deg4 = (hdr >> 24) << 2;
                float di  = rsqrtf((float)((hdr & 0xFFFFFF) + 1));

                float4 acc = make_float4(0.f, 0.f, 0.f, 0.f);
                for (int b = 0; b < deg4; b += 32) {
                    if (b) sl = __ldg(&slots[b + lane]);   // rare (deg>32)
                    int nb = deg4 - b; if (nb > 32) nb = 32;
                    for (int k = 0; k < nb; k += 4) {
                        int   s0 = __shfl_sync(FULL, sl.x, k);
                        int   s1 = __shfl_sync(FULL, sl.x, k + 1);
                        int   s2 = __shfl_sync(FULL, sl.x, k + 2);
                        int   s3 = __shfl_sync(FULL, sl.x, k + 3);
                        float w0 = __int_as_float(__shfl_sync(FULL, sl.y, k));
                        float w1 = __int_as_float(__shfl_sync(FULL, sl.y, k + 1));
                        float w2 = __int_as_float(__shfl_sync(FULL, sl.y, k + 2));
                        float w3 = __int_as_float(__shfl_sync(FULL, sl.y, k + 3));
                        if (lane < 24) {
                            float4 v0 = __ldg((const float4*)(x + (size_t)s0 * FP) + lane);
                            float4 v1 = __ldg((const float4*)(x + (size_t)s1 * FP) + lane);
                            float4 v2 = __ldg((const float4*)(x + (size_t)s2 * FP) + lane);
                            float4 v3 = __ldg((const float4*)(x + (size_t)s3 * FP) + lane);
                            acc.x = fmaf(w0, v0.x, acc.x); acc.y = fmaf(w0, v0.y, acc.y);
                            acc.z = fmaf(w0, v0.z, acc.z); acc.w = fmaf(w0, v0.w, acc.w);
                            acc.x = fmaf(w1, v1.x, acc.x); acc.y = fmaf(w1, v1.y, acc.y);
                            acc.z = fmaf(w1, v1.z, acc.z); acc.w = fmaf(w1, v1.w, acc.w);
                            acc.x = fmaf(w2, v2.x, acc.x); acc.y = fmaf(w2, v2.y, acc.y);
                            acc.z = fmaf(w2, v2.z, acc.z); acc.w = fmaf(w2, v2.w, acc.w);
                            acc.x = fmaf(w3, v3.x, acc.x); acc.y = fmaf(w3, v3.y, acc.y);
                            acc.z = fmaf(w3, v3.z, acc.z); acc.w = fmaf(w3, v3.w, acc.w);
                        }
                    }
                }

                // agg = di * (acc + di * x_self); stage to smem
                if (lane < 24) {
                    float4 xv = __ldg((const float4*)(x + (size_t)node * FP) + lane);
                    acc.x = di * fmaf(di, xv.x, acc.x);
                    acc.y = di * fmaf(di, xv.y, acc.y);
                    acc.z = di * fmaf(di, xv.z, acc.z);
                    acc.w = di * fmaf(di, xv.w, acc.w);
                    ((float4*)buf[warp])[lane] = acc;
                }
                __syncwarp();

                // ---- GRU: packed f32x2 over period pairs, f-outer ----------
                unsigned long long zp[PP / 2], hp[PP / 2];
                {
                    unsigned long long bz2 = pack2(bz_, bz_);
                    unsigned long long bh2 = pack2(bh_, bh_);
                    #pragma unroll
                    for (int q = 0; q < PP / 2; ++q) { zp[q] = bz2; hp[q] = bh2; }
                }
                #pragma unroll
                for (int f = 0; f < FF; ++f) {
                    unsigned long long wz2 = pack2(wz[f], wz[f]);
                    unsigned long long wh2 = pack2(wh[f], wh[f]);
                    #pragma unroll
                    for (int q = 0; q < PP / 2; ++q) {
                        unsigned long long v2 =
                            *(const unsigned long long*)&buf[warp][f * PP + 2 * q];
                        zp[q] = ffma2(v2, wz2, zp[q]);
                        hp[q] = ffma2(v2, wh2, hp[q]);
                    }
                }
                // probs*(1-Z)*tanh(h), Z = 0.5 + 0.5*tanh(z/2)
                //   => (0.5*probs) * (1 - tanh(z/2)) * tanh(h)
                float hacc = 0.f;
                #pragma unroll
                for (int q = 0; q < PP / 2; ++q) {
                    float z0, z1, h0, h1;
                    unpack2(zp[q], z0, z1);
                    unpack2(hp[q], h0, h1);
                    float tz0 = htanh(0.5f * z0);
                    float tz1 = htanh(0.5f * z1);
                    float th0 = htanh(h0);
                    float th1 = htanh(h1);
                    hacc = fmaf(sp2[2 * q],     (1.f - tz0) * th0, hacc);
                    hacc = fmaf(sp2[2 * q + 1], (1.f - tz1) * th1, hacc);
                }
                float hr = fmaxf(hacc, 0.f);     // relu
                __syncwarp();                    // buf reads done before next node

                // ---- readout ------------------------------------------------
                float myout = 0.f;
                #pragma unroll
                for (int p = 0; p < PP; ++p) {
                    float v = hr * sow[p * OO + lane];
                    v += __shfl_xor_sync(FULL, v, 16);
                    v += __shfl_xor_sync(FULL, v, 8);
                    v += __shfl_xor_sync(FULL, v, 4);
                    v += __shfl_xor_sync(FULL, v, 2);
                    v += __shfl_xor_sync(FULL, v, 1);
                    if (lane == p) myout = v + sob[p];
                }
                if (lane < PP) out[node * PP + lane] = myout;
            }
        }
    }
}

// ---------------------------------------------------------------------------
extern "C" void kernel_launch(void* const* d_in, const int* in_sizes, int n_in,
                              void* d_out, int out_size) {
    const float* x    = (const float*)d_in[0];
    const int*   ei   = (const int*)  d_in[1];
    const float* Wz   = (const float*)d_in[2];
    const float* bz   = (const float*)d_in[3];
    // d_in[4], d_in[5]: Wr, br — dead code (H == 0 kills the reset gate)
    const float* Wh   = (const float*)d_in[6];
    const float* bh   = (const float*)d_in[7];
    const float* lzw  = (const float*)d_in[8];
    const float* lzb  = (const float*)d_in[9];
    // d_in[10], d_in[11]: lr_w, lr_b — unused
    const float* lhw  = (const float*)d_in[12];
    const float* lhb  = (const float*)d_in[13];
    const float* att  = (const float*)d_in[14];
    const float* outw = (const float*)d_in[15];
    const float* outb = (const float*)d_in[16];
    float* out = (float*)d_out;

    fused_kernel<<<NBLK, NTHR>>>(x, ei, Wz, bz, Wh, bh, lzw, lzb, lhw, lhb,
                                 att, outw, outb, out);
}

// round 12
// speedup vs baseline: 1.1184x; 1.1184x over previous
#include <cuda_runtime.h>
#include <math.h>

#define NN 20000
#define FF 8
#define PP 12
#define OO 32
#define EE 320000
#define FP 96           // F*P floats per node row
#define SLOTS 96        // max in-degree slots (Poisson(16); guarded)
#define NSM 148
#define NBPS 3
#define NBLK (NSM * NBPS)            // 444 blocks, all co-resident
#define NTHR 256
#define WPB (NTHR / 32)              // 8 warps per block
#define FULL 0xffffffffu

// ---- scratch (static device globals; no allocation allowed) ----
__device__ int      g_cnt[NN];            // in-degree (atomic counters)
__device__ int      g_col[NN * SLOTS];    // slotted adjacency: srcs per dst
__device__ float    g_dinv[NN];           // (in_deg + 1)^-1/2
__device__ float    g_cwz[FF * OO];       // fused Wz @ Lz^T
__device__ float    g_cwh[FF * OO];       // fused Wh @ Lh^T
__device__ float    g_cbz[OO];
__device__ float    g_cbh[OO];
__device__ float    g_probs[PP];
__device__ unsigned g_node_ctr;           // P3 dynamic work counter (reset in P0)
__device__ unsigned g_bar[3];             // monotonic barrier counters (never reset)

// Monotonic grid barrier: all NBLK blocks co-resident (3/SM via launch bounds).
__device__ __forceinline__ void grid_barrier(int id) {
    __syncthreads();
    if (threadIdx.x == 0) {
        __threadfence();                                      // release
        unsigned arrived = atomicAdd(&g_bar[id], 1u) + 1u;
        unsigned target  = ((arrived + NBLK - 1u) / NBLK) * NBLK;
        while (*(volatile unsigned*)&g_bar[id] < target) { }
        __threadfence();                                      // acquire
    }
    __syncthreads();
}

// Packed fp32x2 helpers (Blackwell FFMA2 — only reachable via PTX)
__device__ __forceinline__ unsigned long long pack2(float lo, float hi) {
    unsigned long long r;
    asm("mov.b64 %0, {%1, %2};" : "=l"(r) : "f"(lo), "f"(hi));
    return r;
}
__device__ __forceinline__ void unpack2(unsigned long long v, float& lo, float& hi) {
    asm("mov.b64 {%0, %1}, %2;" : "=f"(lo), "=f"(hi) : "l"(v));
}
__device__ __forceinline__ unsigned long long ffma2(
        unsigned long long a, unsigned long long b, unsigned long long c) {
    unsigned long long d;
    asm("fma.rn.f32x2 %0, %1, %2, %3;" : "=l"(d) : "l"(a), "l"(b), "l"(c));
    return d;
}
// HW tanh (MUFU.TANH), rel err ~1e-5 — far inside the 1e-3 budget
__device__ __forceinline__ float htanh(float x) {
    float r;
    asm("tanh.approx.f32 %0, %1;" : "=f"(r) : "f"(x));
    return r;
}

// Per-node prologue state, loaded one pipeline stage ahead.
struct Prolog {
    int   deg;     // clamped degree
    float di;      // (deg+1)^-1/2 for the node
    int   ci;      // lane's slot col (clamped-valid, masked later)
    float wv;      // dinv[ci] (masked later)
};

__device__ __forceinline__ Prolog load_prolog(int node, int lane) {
    Prolog p;
    // cnt, di, cols all independent -> 3 concurrent chains; dinv[clamp(col)]
    // is the only 2-hop chain. Mask by deg at SELECT time, not load time.
    int   deg = __ldg(&g_cnt[node]);
    p.di  = __ldg(&g_dinv[node]);
    int   raw = __ldg(&g_col[node * SLOTS + lane]);   // always in-bounds (SLOTS>=32)
    int   cl  = raw;                                   // clamp: raw may be stale garbage
    cl = cl < 0 ? 0 : (cl >= NN ? NN - 1 : cl);
    float wv  = __ldg(&g_dinv[cl]);
    if (deg > SLOTS) deg = SLOTS;
    p.deg = deg;
    p.ci  = (lane < deg) ? cl : 0;
    p.wv  = (lane < deg) ? wv : 0.f;
    return p;
}

__global__ void __launch_bounds__(NTHR, NBPS) fused_kernel(
        const float* __restrict__ x,
        const int*   __restrict__ ei,
        const float* __restrict__ Wz,  const float* __restrict__ bz,
        const float* __restrict__ Wh,  const float* __restrict__ bh,
        const float* __restrict__ lzw, const float* __restrict__ lzb,
        const float* __restrict__ lhw, const float* __restrict__ lhb,
        const float* __restrict__ att,
        const float* __restrict__ out_w, const float* __restrict__ out_b,
        float* __restrict__ out) {
    const int t    = threadIdx.x;
    const int lane = t & 31;
    const int warp = t >> 5;                 // 0..7
    const int gid  = blockIdx.x * NTHR + t;
    const int T    = NBLK * NTHR;

    __shared__ float buf[WPB][2][FP];        // GRU staging, per warp, 2 nodes
    __shared__ float sow[PP * OO];           // staged out_w
    __shared__ float sob[PP];                // staged out_b
    __shared__ float sp2[PP];                // 0.5 * softmax(att)

    // ---------------- P0: zero counters + fold weights (blocks 0..2) -------
    for (int j = gid; j < NN; j += T) g_cnt[j] = 0;

    if (blockIdx.x == 0) {                   // W'_z[f][o] = sum_k Wz[f][k]*lzw[o][k]
        int f = t >> 5, o = t & 31;
        float s = 0.f;
        #pragma unroll
        for (int k = 0; k < 32; ++k) s = fmaf(Wz[f * 32 + k], lzw[o * 64 + k], s);
        g_cwz[t] = s;
    } else if (blockIdx.x == 1) {            // W'_h
        int f = t >> 5, o = t & 31;
        float s = 0.f;
        #pragma unroll
        for (int k = 0; k < 32; ++k) s = fmaf(Wh[f * 32 + k], lhw[o * 64 + k], s);
        g_cwh[t] = s;
    } else if (blockIdx.x == 2) {
        if (t < 32) {                        // b'_z
            float s = lzb[t];
            #pragma unroll
            for (int k = 0; k < 32; ++k) s = fmaf(bz[k], lzw[t * 64 + k], s);
            g_cbz[t] = s;
        } else if (t < 64) {                 // b'_h
            int o = t - 32;
            float s = lhb[o];
            #pragma unroll
            for (int k = 0; k < 32; ++k) s = fmaf(bh[k], lhw[o * 64 + k], s);
            g_cbh[o] = s;
        } else if (t == 64) {                // softmax over 12 logits
            float m = att[0];
            for (int p = 1; p < PP; ++p) m = fmaxf(m, att[p]);
            float e[PP], sum = 0.f;
            for (int p = 0; p < PP; ++p) { e[p] = __expf(att[p] - m); sum += e[p]; }
            float inv = 1.f / sum;
            for (int p = 0; p < PP; ++p) g_probs[p] = e[p] * inv;
        }
        if (t == 65) g_node_ctr = 0;         // reset P3 work counter
    }
    grid_barrier(0);

    // ---------------- P1: single-pass slotted scatter -----------------------
    {
        const int4* s4p = (const int4*)ei;
        const int4* d4p = (const int4*)(ei + EE);
        for (int q = gid; q < EE / 4; q += T) {
            int4 s4 = s4p[q];
            int4 d4 = d4p[q];
            int p0 = atomicAdd(&g_cnt[d4.x], 1);
            int p1 = atomicAdd(&g_cnt[d4.y], 1);
            int p2 = atomicAdd(&g_cnt[d4.z], 1);
            int p3 = atomicAdd(&g_cnt[d4.w], 1);
            if (p0 < SLOTS) g_col[d4.x * SLOTS + p0] = s4.x;
            if (p1 < SLOTS) g_col[d4.y * SLOTS + p1] = s4.y;
            if (p2 < SLOTS) g_col[d4.z * SLOTS + p2] = s4.z;
            if (p3 < SLOTS) g_col[d4.w * SLOTS + p3] = s4.w;
        }
    }
    grid_barrier(1);

    // ---------------- P2: dinv = (deg+1)^-1/2 ------------------------------
    for (int j = gid; j < NN; j += T)
        g_dinv[j] = rsqrtf((float)(__ldcg(&g_cnt[j]) + 1));
    grid_barrier(2);

    // ---------------- P3: software-pipelined gather + GRU + readout --------
    {
        if (t < PP) sp2[t] = 0.5f * g_probs[t];   // fold sigmoid's 0.5
        if (t < PP) sob[t] = out_b[t];
        for (int j = t; j < PP * OO; j += NTHR) sow[j] = out_w[j];
        __syncthreads();

        float wzr[FF], whr[FF];
        #pragma unroll
        for (int f = 0; f < FF; ++f) {
            wzr[f] = g_cwz[f * OO + lane];
            whr[f] = g_cwh[f * OO + lane];
        }
        const float bz_ = g_cbz[lane];
        const float bh_ = g_cbh[lane];

        // ---- pipeline: pop pair, prefetch prologues one stage ahead ------
        int base;
        if (lane == 0) base = (int)atomicAdd(&g_node_ctr, 2u);
        base = __shfl_sync(FULL, base, 0);
        Prolog pA, pB;
        if (base < NN) {                     // NN even -> base+1 valid too
            pA = load_prolog(base, lane);
            pB = load_prolog(base + 1, lane);
        }

        while (base < NN) {
            const int nA = base, nB = base + 1;

            // -------- gather both nodes (prologue already resolved) --------
            #pragma unroll
            for (int i = 0; i < 2; ++i) {
                const Prolog& pr = (i == 0) ? pA : pB;
                const int node = (i == 0) ? nA : nB;
                float4 acc = make_float4(0.f, 0.f, 0.f, 0.f);

                int ci = pr.ci; float wv = pr.wv;
                int deg4 = (pr.deg + 3) & ~3;
                for (int b = 0; b < deg4; b += 32) {
                    if (b) {                                  // rare: deg > 32
                        int raw = __ldg(&g_col[node * SLOTS + b + lane]);
                        int cl = raw < 0 ? 0 : (raw >= NN ? NN - 1 : raw);
                        float w2 = __ldg(&g_dinv[cl]);
                        ci = (b + lane < pr.deg) ? cl : 0;
                        wv = (b + lane < pr.deg) ? w2 : 0.f;
                    }
                    int nb = deg4 - b; if (nb > 32) nb = 32;
                    for (int k = 0; k < nb; k += 4) {
                        int   s0 = __shfl_sync(FULL, ci, k);
                        int   s1 = __shfl_sync(FULL, ci, k + 1);
                        int   s2 = __shfl_sync(FULL, ci, k + 2);
                        int   s3 = __shfl_sync(FULL, ci, k + 3);
                        float w0 = __shfl_sync(FULL, wv, k);
                        float w1 = __shfl_sync(FULL, wv, k + 1);
                        float w2 = __shfl_sync(FULL, wv, k + 2);
                        float w3 = __shfl_sync(FULL, wv, k + 3);
                        if (lane < 24) {
                            float4 v0 = __ldg((const float4*)(x + (size_t)s0 * FP) + lane);
                            float4 v1 = __ldg((const float4*)(x + (size_t)s1 * FP) + lane);
                            float4 v2 = __ldg((const float4*)(x + (size_t)s2 * FP) + lane);
                            float4 v3 = __ldg((const float4*)(x + (size_t)s3 * FP) + lane);
                            acc.x = fmaf(w0, v0.x, acc.x); acc.y = fmaf(w0, v0.y, acc.y);
                            acc.z = fmaf(w0, v0.z, acc.z); acc.w = fmaf(w0, v0.w, acc.w);
                            acc.x = fmaf(w1, v1.x, acc.x); acc.y = fmaf(w1, v1.y, acc.y);
                            acc.z = fmaf(w1, v1.z, acc.z); acc.w = fmaf(w1, v1.w, acc.w);
                            acc.x = fmaf(w2, v2.x, acc.x); acc.y = fmaf(w2, v2.y, acc.y);
                            acc.z = fmaf(w2, v2.z, acc.z); acc.w = fmaf(w2, v2.w, acc.w);
                            acc.x = fmaf(w3, v3.x, acc.x); acc.y = fmaf(w3, v3.y, acc.y);
                            acc.z = fmaf(w3, v3.z, acc.z); acc.w = fmaf(w3, v3.w, acc.w);
                        }
                    }
                }
                if (lane < 24) {              // agg = di*(acc + di*x_self)
                    float di = pr.di;
                    float4 xv = __ldg((const float4*)(x + (size_t)node * FP) + lane);
                    acc.x = di * fmaf(di, xv.x, acc.x);
                    acc.y = di * fmaf(di, xv.y, acc.y);
                    acc.z = di * fmaf(di, xv.z, acc.z);
                    acc.w = di * fmaf(di, xv.w, acc.w);
                    ((float4*)buf[warp][i])[lane] = acc;
                }
            }
            __syncwarp();

            // -------- pop + prefetch NEXT pair BEFORE the GRU compute ------
            int nbase;
            if (lane == 0) nbase = (int)atomicAdd(&g_node_ctr, 2u);
            nbase = __shfl_sync(FULL, nbase, 0);
            if (nbase < NN) {
                pA = load_prolog(nbase, lane);       // latency hidden by GRU below
                pB = load_prolog(nbase + 1, lane);
            }

            // -------- GRU + readout for both nodes (pure compute) ----------
            #pragma unroll
            for (int i = 0; i < 2; ++i) {
                const float* bw = buf[warp][i];
                unsigned long long zp[PP / 2], hp[PP / 2];
                {
                    unsigned long long bz2 = pack2(bz_, bz_);
                    unsigned long long bh2 = pack2(bh_, bh_);
                    #pragma unroll
                    for (int q = 0; q < PP / 2; ++q) { zp[q] = bz2; hp[q] = bh2; }
                }
                #pragma unroll
                for (int f = 0; f < FF; ++f) {
                    unsigned long long wz2 = pack2(wzr[f], wzr[f]);
                    unsigned long long wh2 = pack2(whr[f], whr[f]);
                    #pragma unroll
                    for (int q = 0; q < PP / 2; ++q) {
                        unsigned long long v2 =
                            *(const unsigned long long*)&bw[f * PP + 2 * q];
                        zp[q] = ffma2(v2, wz2, zp[q]);
                        hp[q] = ffma2(v2, wh2, hp[q]);
                    }
                }
                // probs*(1-Z)*tanh(h), Z = 0.5 + 0.5*tanh(z/2)
                float hacc = 0.f;
                #pragma unroll
                for (int q = 0; q < PP / 2; ++q) {
                    float z0, z1, h0, h1;
                    unpack2(zp[q], z0, z1);
                    unpack2(hp[q], h0, h1);
                    float tz0 = htanh(0.5f * z0);
                    float tz1 = htanh(0.5f * z1);
                    float th0 = htanh(h0);
                    float th1 = htanh(h1);
                    hacc = fmaf(sp2[2 * q],     (1.f - tz0) * th0, hacc);
                    hacc = fmaf(sp2[2 * q + 1], (1.f - tz1) * th1, hacc);
                }
                float hr = fmaxf(hacc, 0.f);     // relu

                float myout = 0.f;
                #pragma unroll
                for (int p = 0; p < PP; ++p) {
                    float v = hr * sow[p * OO + lane];
                    v += __shfl_xor_sync(FULL, v, 16);
                    v += __shfl_xor_sync(FULL, v, 8);
                    v += __shfl_xor_sync(FULL, v, 4);
                    v += __shfl_xor_sync(FULL, v, 2);
                    v += __shfl_xor_sync(FULL, v, 1);
                    if (lane == p) myout = v + sob[p];
                }
                if (lane < PP) out[(base + i) * PP + lane] = myout;
            }
            __syncwarp();                    // buf reads done before next pair
            base = nbase;
        }
    }
}

// ---------------------------------------------------------------------------
extern "C" void kernel_launch(void* const* d_in, const int* in_sizes, int n_in,
                              void* d_out, int out_size) {
    const float* x    = (const float*)d_in[0];
    const int*   ei   = (const int*)  d_in[1];
    const float* Wz   = (const float*)d_in[2];
    const float* bz   = (const float*)d_in[3];
    // d_in[4], d_in[5]: Wr, br — dead code (H == 0 kills the reset gate)
    const float* Wh   = (const float*)d_in[6];
    const float* bh   = (const float*)d_in[7];
    const float* lzw  = (const float*)d_in[8];
    const float* lzb  = (const float*)d_in[9];
    // d_in[10], d_in[11]: lr_w, lr_b — unused
    const float* lhw  = (const float*)d_in[12];
    const float* lhb  = (const float*)d_in[13];
    const float* att  = (const float*)d_in[14];
    const float* outw = (const float*)d_in[15];
    const float* outb = (const float*)d_in[16];
    float* out = (float*)d_out;

    fused_kernel<<<NBLK, NTHR>>>(x, ei, Wz, bz, Wh, bh, lzw, lzb, lhw, lhb,
                                 att, outw, outb, out);
}